// round 11
// baseline (speedup 1.0000x reference)
#include <cuda_runtime.h>
#include <cuda_bf16.h>
#include <mma.h>
#include <cstdint>

using namespace nvcuda;
typedef __nv_bfloat16 bf16;
typedef __nv_bfloat162 bf162;

// ---------------- problem constants ----------------
constexpr int Bz  = 2;
constexpr int Ss  = 2048;
constexpr int HID = 2048;
constexpr int Hh  = 16;
constexpr int KVh = 8;
constexpr int Dd  = 128;
constexpr int MROWS = Bz * Ss;                 // 4096
constexpr int NQKV  = (Hh + 2 * KVh) * Dd;     // 4096
constexpr float SCALE_Q = 0.08838834764831845f; // 1/sqrt(128)

// ---------------- scratch (static device memory) ----------------
__device__ bf16 g_xh[MROWS * HID], g_xl[MROWS * HID];
__device__ bf16 g_wh[NQKV * HID],  g_wl[NQKV * HID];
__device__ bf16 g_owh[HID * Hh * Dd], g_owl[HID * Hh * Dd];
__device__ float g_qkv[(size_t)MROWS * NQKV];
constexpr size_t QN = (size_t)Bz * Hh * Ss * Dd;
constexpr size_t KN = (size_t)Bz * KVh * Ss * Dd;
__device__ bf16 g_qh[QN], g_ql[QN];
__device__ bf16 g_kh[KN], g_kl[KN];
__device__ bf16 g_vh[KN], g_vl[KN];
__device__ bf16 g_vth[KN], g_vtl[KN];          // V transposed [B,KV,D,S]
constexpr size_t SCN = (size_t)Bz * Hh * Ss * Ss;
__device__ float g_sc[SCN];
__device__ bf16 g_ph[SCN], g_pl[SCN];
__device__ bf16 g_aoh[(size_t)MROWS * Hh * Dd], g_aol[(size_t)MROWS * Hh * Dd];

// ---------------- helpers ----------------
__device__ __forceinline__ uint32_t s2u(const void* p) {
    uint32_t a;
    asm("{ .reg .u64 t; cvta.to.shared.u64 t, %1; cvt.u32.u64 %0, t; }" : "=r"(a) : "l"(p));
    return a;
}
__device__ __forceinline__ void cpa16(uint32_t dst, const void* src) {
    asm volatile("cp.async.cg.shared.global [%0], [%1], 16;" :: "r"(dst), "l"(src) : "memory");
}
#define CP_COMMIT() asm volatile("cp.async.commit_group;" ::: "memory")
#define CP_WAIT(n)  asm volatile("cp.async.wait_group %0;" :: "n"(n) : "memory")

__device__ __forceinline__ void wsb(bf16* __restrict__ hi, bf16* __restrict__ lo,
                                    long long i, float v) {
    bf16 h = __float2bfloat16(v);
    hi[i] = h;
    lo[i] = __float2bfloat16(v - __bfloat162float(h));
}

// ---------------- HMMA bf16-split batched GEMM (R7-proven mainloop) ----------
// C[m,n] = sum_k A[m,k]*B[n,k], A = Ah+Al, B = Bh+Bl (bf16 hi/lo of fp32).
// Terms: Ah*Bh + Al*Bh + Ah*Bl. CTA tile 128x128, K-chunk 32, cp.async x2 buf.
// LDA=40 (80B pitch): conflict-free ldmatrix. 2 CTAs/SM.
// EPI 0: fp32 C; EPI 1: bf16 split Chi/Clo.
// causal 0: none; 1: skip n0>m0; 2: Kend = m0+128.
// Causal kernels launch heavy tiles first (y-index flip; register-neutral).
constexpr int LDA   = 40;
constexpr int MATB  = 128 * LDA * 2;          // 10240 B per matrix tile
constexpr int STAGE = 4 * MATB;               // 40960 B
constexpr int SMEM_MM = 2 * STAGE;            // 81920 B
constexpr int CPITCH = 132;                   // fp32 staging pitch; mult of 4 (wmma)

template <int EPI>
__global__ __launch_bounds__(256, 2) void k_mm(
    const bf16* __restrict__ Ah, const bf16* __restrict__ Al,
    const bf16* __restrict__ Bh, const bf16* __restrict__ Bl,
    float* __restrict__ C, bf16* __restrict__ Chi, bf16* __restrict__ Clo,
    int K, int ldc,
    long long aSB, long long aSH, long long bSB, long long bSH,
    long long cSB, long long cSH, int Hdim, int gqa, int causal) {
    const int m0 = (causal ? (gridDim.y - 1 - blockIdx.y) : blockIdx.y) * 128;
    const int n0 = blockIdx.x * 128;
    if (causal == 1 && n0 > m0) return;

    extern __shared__ __align__(16) char smem[];
    const uint32_t sb = s2u(smem);
    const int tid = threadIdx.x, wid = tid >> 5;

    const int z = blockIdx.z, b = z / Hdim, h = z - b * Hdim;
    const bf16* pAh = Ah + (long long)b * aSB + (long long)h * aSH;
    const bf16* pAl = Al + (long long)b * aSB + (long long)h * aSH;
    const bf16* pBh = Bh + (long long)b * bSB + (long long)(h / gqa) * bSH;
    const bf16* pBl = Bl + (long long)b * bSB + (long long)(h / gqa) * bSH;
    const long long cOff = (long long)b * cSB + (long long)h * cSH;

    uint32_t sdst[2];
    long long offA[2];
    const long long dBA = (long long)(n0 - m0) * K;
#pragma unroll
    for (int i = 0; i < 2; i++) {
        int idx = i * 256 + tid, r = idx >> 2, c8 = (idx & 3) << 3;
        sdst[i] = (uint32_t)(r * (LDA * 2) + c8 * 2);
        offA[i] = (long long)(m0 + r) * K + c8;
    }

    const int Kend = (causal == 2) ? (m0 + 128) : K;
    const int nch = Kend >> 5;

    auto loadChunk = [&](int c, int st) {
        const uint32_t base = sb + st * STAGE;
        const long long kb = (long long)c * 32;
#pragma unroll
        for (int i = 0; i < 2; i++) {
            const long long oa = offA[i] + kb, ob = oa + dBA;
            cpa16(base + sdst[i],            pAh + oa);
            cpa16(base + MATB + sdst[i],     pAl + oa);
            cpa16(base + 2 * MATB + sdst[i], pBh + ob);
            cpa16(base + 3 * MATB + sdst[i], pBl + ob);
        }
        CP_COMMIT();
    };

    const int wm = (wid & 3) * 32;
    const int wn = (wid >> 2) * 64;

    wmma::fragment<wmma::accumulator, 16, 16, 16, float> acc[2][4];
#pragma unroll
    for (int i = 0; i < 2; i++)
#pragma unroll
        for (int j = 0; j < 4; j++) wmma::fill_fragment(acc[i][j], 0.0f);

    loadChunk(0, 0);
    for (int c = 0; c < nch; c++) {
        if (c + 1 < nch) { loadChunk(c + 1, (c + 1) & 1); CP_WAIT(1); }
        else             { CP_WAIT(0); }
        __syncthreads();

        const char* st = smem + (c & 1) * STAGE;
        const bf16* sAh = (const bf16*)(st);
        const bf16* sAl = (const bf16*)(st + MATB);
        const bf16* sBh = (const bf16*)(st + 2 * MATB);
        const bf16* sBl = (const bf16*)(st + 3 * MATB);

#pragma unroll
        for (int ks = 0; ks < 32; ks += 16) {
            wmma::fragment<wmma::matrix_a, 16, 16, 16, bf16, wmma::row_major> ah[2], al[2];
#pragma unroll
            for (int i = 0; i < 2; i++) {
                wmma::load_matrix_sync(ah[i], sAh + (wm + 16 * i) * LDA + ks, LDA);
                wmma::load_matrix_sync(al[i], sAl + (wm + 16 * i) * LDA + ks, LDA);
            }
#pragma unroll
            for (int j = 0; j < 4; j++) {
                wmma::fragment<wmma::matrix_b, 16, 16, 16, bf16, wmma::col_major> bh, bl;
                wmma::load_matrix_sync(bh, sBh + (wn + 16 * j) * LDA + ks, LDA);
                wmma::load_matrix_sync(bl, sBl + (wn + 16 * j) * LDA + ks, LDA);
#pragma unroll
                for (int i = 0; i < 2; i++) {
                    wmma::mma_sync(acc[i][j], al[i], bh, acc[i][j]);
                    wmma::mma_sync(acc[i][j], ah[i], bl, acc[i][j]);
                    wmma::mma_sync(acc[i][j], ah[i], bh, acc[i][j]);
                }
            }
        }
        __syncthreads();
    }

    if constexpr (EPI == 0) {
        float* pc = C + cOff;
#pragma unroll
        for (int i = 0; i < 2; i++)
#pragma unroll
            for (int j = 0; j < 4; j++)
                wmma::store_matrix_sync(
                    pc + (long long)(m0 + wm + 16 * i) * ldc + n0 + wn + 16 * j,
                    acc[i][j], ldc, wmma::mem_row_major);
    } else {
        float* cst = (float*)smem;
#pragma unroll
        for (int i = 0; i < 2; i++)
#pragma unroll
            for (int j = 0; j < 4; j++)
                wmma::store_matrix_sync(cst + (wm + 16 * i) * CPITCH + wn + 16 * j,
                                        acc[i][j], CPITCH, wmma::mem_row_major);
        __syncthreads();
        const int row = tid >> 1, cb = (tid & 1) * 64;
        bf16* ph_ = Chi + cOff + (long long)(m0 + row) * ldc + n0 + cb;
        bf16* pl_ = Clo + cOff + (long long)(m0 + row) * ldc + n0 + cb;
        const float* src = cst + row * CPITCH + cb;
#pragma unroll
        for (int i = 0; i < 32; i++) {
            float a0 = src[2 * i], a1 = src[2 * i + 1];
            bf162 hh, ll;
            hh.x = __float2bfloat16(a0);
            ll.x = __float2bfloat16(a0 - __bfloat162float(hh.x));
            hh.y = __float2bfloat16(a1);
            ll.y = __float2bfloat16(a1 - __bfloat162float(hh.y));
            reinterpret_cast<bf162*>(ph_)[i] = hh;
            reinterpret_cast<bf162*>(pl_)[i] = ll;
        }
    }
}

// ---------------- fused input split: all 5 tensors in one launch -------------
__device__ __forceinline__ void split4(float4 v, bf16* __restrict__ hi,
                                       bf16* __restrict__ lo, int i) {
    bf162 h0, h1, l0, l1;
    h0.x = __float2bfloat16(v.x); l0.x = __float2bfloat16(v.x - __bfloat162float(h0.x));
    h0.y = __float2bfloat16(v.y); l0.y = __float2bfloat16(v.y - __bfloat162float(h0.y));
    h1.x = __float2bfloat16(v.z); l1.x = __float2bfloat16(v.z - __bfloat162float(h1.x));
    h1.y = __float2bfloat16(v.w); l1.y = __float2bfloat16(v.w - __bfloat162float(h1.y));
    reinterpret_cast<bf162*>(hi)[2 * i]     = h0;
    reinterpret_cast<bf162*>(hi)[2 * i + 1] = h1;
    reinterpret_cast<bf162*>(lo)[2 * i]     = l0;
    reinterpret_cast<bf162*>(lo)[2 * i + 1] = l1;
}

constexpr int F4_X  = MROWS * HID / 4;              // 524288
constexpr int F4_QW = Hh * Dd * HID / 4;            // 1048576
constexpr int F4_KW = KVh * Dd * HID / 4;           // 524288
constexpr int F4_TOT = F4_X + F4_QW + 2 * F4_KW + (HID * Hh * Dd / 4);

__global__ void k_split_all(const float* __restrict__ x, const float* __restrict__ qw,
                            const float* __restrict__ kw, const float* __restrict__ vw,
                            const float* __restrict__ ow) {
    int i = blockIdx.x * 256 + threadIdx.x;
    if (i >= F4_TOT) return;
    if (i < F4_X) {
        split4(((const float4*)x)[i], g_xh, g_xl, i);
    } else if (i < F4_X + F4_QW) {
        int j = i - F4_X;
        split4(((const float4*)qw)[j], g_wh, g_wl, j);
    } else if (i < F4_X + F4_QW + F4_KW) {
        int j = i - (F4_X + F4_QW);
        split4(((const float4*)kw)[j], g_wh + Hh * Dd * HID, g_wl + Hh * Dd * HID, j);
    } else if (i < F4_X + F4_QW + 2 * F4_KW) {
        int j = i - (F4_X + F4_QW + F4_KW);
        split4(((const float4*)vw)[j], g_wh + (Hh + KVh) * Dd * HID,
               g_wl + (Hh + KVh) * Dd * HID, j);
    } else {
        int j = i - (F4_X + F4_QW + 2 * F4_KW);
        split4(((const float4*)ow)[j], g_owh, g_owl, j);
    }
}

// ---------------- QKV post: RMSNorm + RoPE + bf16 split ----------------
__global__ void k_qkvpost(const float* __restrict__ qkv, const float* __restrict__ pe,
                          const float* __restrict__ qnw, const float* __restrict__ knw,
                          bf16* __restrict__ qh, bf16* __restrict__ ql,
                          bf16* __restrict__ kh, bf16* __restrict__ kl,
                          bf16* __restrict__ vh, bf16* __restrict__ vl) {
    const int task = blockIdx.x * 4 + (threadIdx.x >> 5);
    const int lane = threadIdx.x & 31;

    if (task < 65536) {  // Q
        const int bs = task >> 4, h = task & 15;
        const float* src = qkv + (long long)bs * NQKV + h * Dd;
        float x0 = src[lane], x1 = src[lane + 32], x2 = src[lane + 64], x3 = src[lane + 96];
        float ss = x0 * x0 + x1 * x1 + x2 * x2 + x3 * x3;
#pragma unroll
        for (int o = 16; o; o >>= 1) ss += __shfl_xor_sync(0xffffffffu, ss, o);
        float inv = rsqrtf(ss * (1.0f / 128.0f) + 1e-6f);
        float n0 = x0 * inv * qnw[lane],      n1 = x1 * inv * qnw[lane + 32];
        float n2 = x2 * inv * qnw[lane + 64], n3 = x3 * inv * qnw[lane + 96];
        const float* per = pe + (long long)bs * Dd;
        float c0 = per[lane],      s0 = per[64 + lane];
        float c1 = per[32 + lane], s1 = per[96 + lane];
        float o0 = (n0 * c0 - n2 * s0) * SCALE_Q;
        float o1 = (n1 * c1 - n3 * s1) * SCALE_Q;
        float o2 = (n0 * s0 + n2 * c0) * SCALE_Q;
        float o3 = (n1 * s1 + n3 * c1) * SCALE_Q;
        const int b = bs >> 11, s = bs & 2047;
        long long base = ((long long)(b * Hh + h) * Ss + s) * Dd;
        wsb(qh, ql, base + lane, o0);       wsb(qh, ql, base + lane + 32, o1);
        wsb(qh, ql, base + lane + 64, o2);  wsb(qh, ql, base + lane + 96, o3);
    } else if (task < 98304) {  // K
        const int t = task - 65536;
        const int bs = t >> 3, kvh = t & 7;
        const float* src = qkv + (long long)bs * NQKV + Hh * Dd + kvh * Dd;
        float x0 = src[lane], x1 = src[lane + 32], x2 = src[lane + 64], x3 = src[lane + 96];
        float ss = x0 * x0 + x1 * x1 + x2 * x2 + x3 * x3;
#pragma unroll
        for (int o = 16; o; o >>= 1) ss += __shfl_xor_sync(0xffffffffu, ss, o);
        float inv = rsqrtf(ss * (1.0f / 128.0f) + 1e-6f);
        float n0 = x0 * inv * knw[lane],      n1 = x1 * inv * knw[lane + 32];
        float n2 = x2 * inv * knw[lane + 64], n3 = x3 * inv * knw[lane + 96];
        const float* per = pe + (long long)bs * Dd;
        float c0 = per[lane],      s0 = per[64 + lane];
        float c1 = per[32 + lane], s1 = per[96 + lane];
        float o0 = n0 * c0 - n2 * s0, o1 = n1 * c1 - n3 * s1;
        float o2 = n0 * s0 + n2 * c0, o3 = n1 * s1 + n3 * c1;
        const int b = bs >> 11, s = bs & 2047;
        long long base = ((long long)(b * KVh + kvh) * Ss + s) * Dd;
        wsb(kh, kl, base + lane, o0);       wsb(kh, kl, base + lane + 32, o1);
        wsb(kh, kl, base + lane + 64, o2);  wsb(kh, kl, base + lane + 96, o3);
    } else {  // V
        const int t = task - 98304;
        const int bs = t >> 3, kvh = t & 7;
        const float* src = qkv + (long long)bs * NQKV + (Hh + KVh) * Dd + kvh * Dd;
        const int b = bs >> 11, s = bs & 2047;
        long long base = ((long long)(b * KVh + kvh) * Ss + s) * Dd;
        wsb(vh, vl, base + lane,      src[lane]);
        wsb(vh, vl, base + lane + 32, src[lane + 32]);
        wsb(vh, vl, base + lane + 64, src[lane + 64]);
        wsb(vh, vl, base + lane + 96, src[lane + 96]);
    }
}

// ---------------- V transpose: [B,KV,S,D] -> [B,KV,D,S] (hi+lo) ----------------
__global__ void k_vt(const bf16* __restrict__ vh, const bf16* __restrict__ vl,
                     bf16* __restrict__ vth, bf16* __restrict__ vtl) {
    __shared__ bf16 th[32][33], tl[32][33];
    const int bz = blockIdx.z;
    const long long base = (long long)bz * Ss * Dd;
    const int s0 = blockIdx.x * 32, d0 = blockIdx.y * 32;
    const int tx = threadIdx.x, ty = threadIdx.y;
#pragma unroll
    for (int j = 0; j < 4; j++) {
        int r = ty + j * 8;
        th[r][tx] = vh[base + (long long)(s0 + r) * Dd + d0 + tx];
        tl[r][tx] = vl[base + (long long)(s0 + r) * Dd + d0 + tx];
    }
    __syncthreads();
#pragma unroll
    for (int j = 0; j < 4; j++) {
        int r = ty + j * 8;
        vth[base + (long long)(d0 + r) * Ss + s0 + tx] = th[tx][r];
        vtl[base + (long long)(d0 + r) * Ss + s0 + tx] = tl[tx][r];
    }
}

// ---------------- causal softmax: vectorized (float2 in, bf162 out) ----------
__global__ void k_softmax(const float* __restrict__ sc, bf16* __restrict__ ph,
                          bf16* __restrict__ pl) {
    const int row = blockIdx.x;           // [0, B*H*S)
    const int s = row & (Ss - 1);
    const float* p = sc + (long long)row * Ss;
    bf16* oh = ph + (long long)row * Ss;
    bf16* ol = pl + (long long)row * Ss;
    const int L = s + 1;
    const int tid = threadIdx.x;
    const int base = tid * 2;

    float2 ev[8];
    int cnt = 0;
    float mx = -3.4e38f;
    float tailv = 0.0f;
    bool hasTail = false;
    int i = base;
    for (; i + 1 < L; i += 256) {
        float2 v = *(const float2*)(p + i);
        ev[cnt++] = v;
        mx = fmaxf(mx, fmaxf(v.x, v.y));
    }
    if (i < L) { tailv = p[i]; hasTail = true; mx = fmaxf(mx, tailv); }

#pragma unroll
    for (int o = 16; o; o >>= 1) mx = fmaxf(mx, __shfl_xor_sync(0xffffffffu, mx, o));
    __shared__ float shm[4], shs[4];
    if ((tid & 31) == 0) shm[tid >> 5] = mx;
    __syncthreads();
    mx = fmaxf(fmaxf(shm[0], shm[1]), fmaxf(shm[2], shm[3]));

    float sum = 0.0f;
    for (int j = 0; j < cnt; j++) {
        float2 e;
        e.x = __expf(ev[j].x - mx);
        e.y = __expf(ev[j].y - mx);
        ev[j] = e;
        sum += e.x + e.y;
    }
    if (hasTail) { tailv = __expf(tailv - mx); sum += tailv; }
#pragma unroll
    for (int o = 16; o; o >>= 1) sum += __shfl_xor_sync(0xffffffffu, sum, o);
    if ((tid & 31) == 0) shs[tid >> 5] = sum;
    __syncthreads();
    sum = shs[0] + shs[1] + shs[2] + shs[3];
    const float inv = 1.0f / sum;

    i = base;
    for (int j = 0; j < cnt; j++, i += 256) {
        float v0 = ev[j].x * inv, v1 = ev[j].y * inv;
        bf162 hh, ll;
        hh.x = __float2bfloat16(v0);
        ll.x = __float2bfloat16(v0 - __bfloat162float(hh.x));
        hh.y = __float2bfloat16(v1);
        ll.y = __float2bfloat16(v1 - __bfloat162float(hh.y));
        *(bf162*)(oh + i) = hh;
        *(bf162*)(ol + i) = ll;
    }
    if (hasTail) {
        float v = tailv * inv;
        bf16 h = __float2bfloat16(v);
        oh[i] = h;
        ol[i] = __float2bfloat16(v - __bfloat162float(h));
    }
    const int tileEnd = ((s >> 7) << 7) + 128;  // pad to 128-tile boundary for AV
    bf16 z = __float2bfloat16(0.0f);
    for (int j = L + tid; j < tileEnd; j += 128) { oh[j] = z; ol[j] = z; }
}

// ---------------- launch -----------------------------------------------------
extern "C" void kernel_launch(void* const* d_in, const int* in_sizes, int n_in,
                              void* d_out, int out_size) {
    (void)in_sizes; (void)n_in; (void)out_size;
    const float* x   = (const float*)d_in[0];
    const float* pe  = (const float*)d_in[1];
    const float* qw  = (const float*)d_in[2];
    const float* kw  = (const float*)d_in[3];
    const float* vw  = (const float*)d_in[4];
    const float* ow  = (const float*)d_in[5];
    const float* qnw = (const float*)d_in[6];
    const float* knw = (const float*)d_in[7];
    float* out = (float*)d_out;

    bf16 *xh, *xl, *wh, *wl, *owh, *owl;
    bf16 *qh, *ql, *kh, *kl, *vh, *vl, *vth, *vtl, *ph, *pl, *aoh, *aol;
    float *qkvp, *sc;
    cudaGetSymbolAddress((void**)&xh, g_xh);   cudaGetSymbolAddress((void**)&xl, g_xl);
    cudaGetSymbolAddress((void**)&wh, g_wh);   cudaGetSymbolAddress((void**)&wl, g_wl);
    cudaGetSymbolAddress((void**)&owh, g_owh); cudaGetSymbolAddress((void**)&owl, g_owl);
    cudaGetSymbolAddress((void**)&qkvp, g_qkv);
    cudaGetSymbolAddress((void**)&qh, g_qh);   cudaGetSymbolAddress((void**)&ql, g_ql);
    cudaGetSymbolAddress((void**)&kh, g_kh);   cudaGetSymbolAddress((void**)&kl, g_kl);
    cudaGetSymbolAddress((void**)&vh, g_vh);   cudaGetSymbolAddress((void**)&vl, g_vl);
    cudaGetSymbolAddress((void**)&vth, g_vth); cudaGetSymbolAddress((void**)&vtl, g_vtl);
    cudaGetSymbolAddress((void**)&sc, g_sc);
    cudaGetSymbolAddress((void**)&ph, g_ph);   cudaGetSymbolAddress((void**)&pl, g_pl);
    cudaGetSymbolAddress((void**)&aoh, g_aoh); cudaGetSymbolAddress((void**)&aol, g_aol);

    cudaFuncSetAttribute(k_mm<0>, cudaFuncAttributeMaxDynamicSharedMemorySize, SMEM_MM);
    cudaFuncSetAttribute(k_mm<1>, cudaFuncAttributeMaxDynamicSharedMemorySize, SMEM_MM);

    // 1) bf16 splits of x and all weights (single launch)
    k_split_all<<<(F4_TOT + 255) / 256, 256>>>(x, qw, kw, vw, ow);

    // 2) QKV projection: [4096,2048] @ [4096,2048]^T -> g_qkv [4096,4096] fp32
    {
        dim3 g(NQKV / 128, MROWS / 128, 1);
        k_mm<0><<<g, 256, SMEM_MM>>>(xh, xl, wh, wl, qkvp, nullptr, nullptr,
                                     HID, NQKV, 0, 0, 0, 0, 0, 0, 1, 1, 0);
    }

    // 3) RMSNorm + RoPE + bf16 split -> q/k/v [B,(KV)H,S,D]
    k_qkvpost<<<32768, 128>>>(qkvp, pe, qnw, knw, qh, ql, kh, kl, vh, vl);

    // 4) V transpose -> [B,KV,D,S]
    {
        dim3 g(Ss / 32, Dd / 32, Bz * KVh);
        k_vt<<<g, dim3(32, 8)>>>(vh, vl, vth, vtl);
    }

    // 5) scores = q @ k^T (causal tile-skip) -> g_sc fp32 [B,H,S,S]
    {
        dim3 g(Ss / 128, Ss / 128, Bz * Hh);
        k_mm<0><<<g, 256, SMEM_MM>>>(
            qh, ql, kh, kl, sc, nullptr, nullptr, Dd, Ss,
            (long long)Hh * Ss * Dd, (long long)Ss * Dd,
            (long long)KVh * Ss * Dd, (long long)Ss * Dd,
            (long long)Hh * Ss * Ss, (long long)Ss * Ss,
            Hh, Hh / KVh, 1);
    }

    // 6) softmax -> P bf16 hi/lo, zero-padded to tile edge (vectorized)
    k_softmax<<<Bz * Hh * Ss, 128>>>(sc, ph, pl);

    // 7) attnout = P @ V^T (K-trimmed, heavy-first), bf16 hi/lo out [B,S,H,D]
    {
        dim3 g(1, Ss / 128, Bz * Hh);
        k_mm<1><<<g, 256, SMEM_MM>>>(
            ph, pl, vth, vtl, nullptr, aoh, aol, Ss, Hh * Dd,
            (long long)Hh * Ss * Ss, (long long)Ss * Ss,
            (long long)KVh * Dd * Ss, (long long)Dd * Ss,
            (long long)Ss * Hh * Dd, (long long)Dd,
            Hh, Hh / KVh, 2);
    }

    // 8) out = attnout @ o_w^T -> d_out [4096,2048] fp32
    {
        dim3 g(HID / 128, MROWS / 128, 1);
        k_mm<0><<<g, 256, SMEM_MM>>>(aoh, aol, owh, owl, out, nullptr, nullptr,
                                     Hh * Dd, HID, 0, 0, 0, 0, 0, 0, 1, 1, 0);
    }
}

// round 12
// speedup vs baseline: 1.5045x; 1.5045x over previous
#include <cuda_runtime.h>
#include <cuda_bf16.h>
#include <mma.h>
#include <cstdint>

using namespace nvcuda;
typedef __nv_bfloat16 bf16;
typedef __nv_bfloat162 bf162;

// ---------------- problem constants ----------------
constexpr int Bz  = 2;
constexpr int Ss  = 2048;
constexpr int HID = 2048;
constexpr int Hh  = 16;
constexpr int KVh = 8;
constexpr int Dd  = 128;
constexpr int MROWS = Bz * Ss;                 // 4096
constexpr int NQKV  = (Hh + 2 * KVh) * Dd;     // 4096
constexpr float SCALE_Q = 0.08838834764831845f; // 1/sqrt(128)

// ---------------- scratch (static device memory) ----------------
__device__ bf16 g_xh[MROWS * HID], g_xl[MROWS * HID];
__device__ bf16 g_wh[NQKV * HID],  g_wl[NQKV * HID];
__device__ bf16 g_owh[HID * Hh * Dd], g_owl[HID * Hh * Dd];
__device__ float g_qkv[(size_t)MROWS * NQKV];
constexpr size_t QN = (size_t)Bz * Hh * Ss * Dd;
constexpr size_t KN = (size_t)Bz * KVh * Ss * Dd;
__device__ bf16 g_qh[QN], g_ql[QN];
__device__ bf16 g_kh[KN], g_kl[KN];
__device__ bf16 g_vh[KN], g_vl[KN];
__device__ bf16 g_vth[KN], g_vtl[KN];          // V transposed [B,KV,D,S]
constexpr size_t SCN = (size_t)Bz * Hh * Ss * Ss;
__device__ float g_sc[SCN];
__device__ bf16 g_ph[SCN], g_pl[SCN];
__device__ bf16 g_aoh[(size_t)MROWS * Hh * Dd], g_aol[(size_t)MROWS * Hh * Dd];

// ---------------- helpers ----------------
__device__ __forceinline__ uint32_t s2u(const void* p) {
    uint32_t a;
    asm("{ .reg .u64 t; cvta.to.shared.u64 t, %1; cvt.u32.u64 %0, t; }" : "=r"(a) : "l"(p));
    return a;
}
__device__ __forceinline__ void cpa16(uint32_t dst, const void* src) {
    asm volatile("cp.async.cg.shared.global [%0], [%1], 16;" :: "r"(dst), "l"(src) : "memory");
}
#define CP_COMMIT() asm volatile("cp.async.commit_group;" ::: "memory")
#define CP_WAIT(n)  asm volatile("cp.async.wait_group %0;" :: "n"(n) : "memory")

__device__ __forceinline__ void wsb(bf16* __restrict__ hi, bf16* __restrict__ lo,
                                    long long i, float v) {
    bf16 h = __float2bfloat16(v);
    hi[i] = h;
    lo[i] = __float2bfloat16(v - __bfloat162float(h));
}

// ---------------- HMMA bf16-split batched GEMM (R7 byte-identical) ----------
// C[m,n] = sum_k A[m,k]*B[n,k], A = Ah+Al, B = Bh+Bl (bf16 hi/lo of fp32).
// Terms: Ah*Bh + Al*Bh + Ah*Bl. CTA tile 128x128, K-chunk 32, cp.async x2 buf.
// LDA=40 (80B pitch): conflict-free ldmatrix. 2 CTAs/SM.
// EPI 0: fp32 C; EPI 1: bf16 split Chi/Clo.
// causal 0: none; 1: skip n0>m0; 2: Kend = m0+128.
constexpr int LDA   = 40;                     // smem leading dim (elems); 80B rows
constexpr int MATB  = 128 * LDA * 2;          // 10240 B per matrix tile
constexpr int STAGE = 4 * MATB;               // 40960 B
constexpr int SMEM_MM = 2 * STAGE;            // 81920 B
constexpr int CPITCH = 132;                   // fp32 staging pitch; mult of 4 (wmma)

template <int EPI>
__global__ __launch_bounds__(256, 2) void k_mm(
    const bf16* __restrict__ Ah, const bf16* __restrict__ Al,
    const bf16* __restrict__ Bh, const bf16* __restrict__ Bl,
    float* __restrict__ C, bf16* __restrict__ Chi, bf16* __restrict__ Clo,
    int K, int ldc,
    long long aSB, long long aSH, long long bSB, long long bSH,
    long long cSB, long long cSH, int Hdim, int gqa, int causal) {
    const int m0 = blockIdx.y * 128, n0 = blockIdx.x * 128;
    if (causal == 1 && n0 > m0) return;

    extern __shared__ __align__(16) char smem[];
    const uint32_t sb = s2u(smem);
    const int tid = threadIdx.x, wid = tid >> 5;

    const int z = blockIdx.z, b = z / Hdim, h = z - b * Hdim;
    const bf16* pAh = Ah + (long long)b * aSB + (long long)h * aSH;
    const bf16* pAl = Al + (long long)b * aSB + (long long)h * aSH;
    const bf16* pBh = Bh + (long long)b * bSB + (long long)(h / gqa) * bSH;
    const bf16* pBl = Bl + (long long)b * bSB + (long long)(h / gqa) * bSH;
    const long long cOff = (long long)b * cSB + (long long)h * cSH;

    uint32_t sdst[2];
    long long offA[2];
    const long long dBA = (long long)(n0 - m0) * K;
#pragma unroll
    for (int i = 0; i < 2; i++) {
        int idx = i * 256 + tid, r = idx >> 2, c8 = (idx & 3) << 3;
        sdst[i] = (uint32_t)(r * (LDA * 2) + c8 * 2);
        offA[i] = (long long)(m0 + r) * K + c8;
    }

    const int Kend = (causal == 2) ? (m0 + 128) : K;
    const int nch = Kend >> 5;

    auto loadChunk = [&](int c, int st) {
        const uint32_t base = sb + st * STAGE;
        const long long kb = (long long)c * 32;
#pragma unroll
        for (int i = 0; i < 2; i++) {
            const long long oa = offA[i] + kb, ob = oa + dBA;
            cpa16(base + sdst[i],            pAh + oa);
            cpa16(base + MATB + sdst[i],     pAl + oa);
            cpa16(base + 2 * MATB + sdst[i], pBh + ob);
            cpa16(base + 3 * MATB + sdst[i], pBl + ob);
        }
        CP_COMMIT();
    };

    const int wm = (wid & 3) * 32;
    const int wn = (wid >> 2) * 64;

    wmma::fragment<wmma::accumulator, 16, 16, 16, float> acc[2][4];
#pragma unroll
    for (int i = 0; i < 2; i++)
#pragma unroll
        for (int j = 0; j < 4; j++) wmma::fill_fragment(acc[i][j], 0.0f);

    loadChunk(0, 0);
    for (int c = 0; c < nch; c++) {
        if (c + 1 < nch) { loadChunk(c + 1, (c + 1) & 1); CP_WAIT(1); }
        else             { CP_WAIT(0); }
        __syncthreads();

        const char* st = smem + (c & 1) * STAGE;
        const bf16* sAh = (const bf16*)(st);
        const bf16* sAl = (const bf16*)(st + MATB);
        const bf16* sBh = (const bf16*)(st + 2 * MATB);
        const bf16* sBl = (const bf16*)(st + 3 * MATB);

#pragma unroll
        for (int ks = 0; ks < 32; ks += 16) {
            wmma::fragment<wmma::matrix_a, 16, 16, 16, bf16, wmma::row_major> ah[2], al[2];
#pragma unroll
            for (int i = 0; i < 2; i++) {
                wmma::load_matrix_sync(ah[i], sAh + (wm + 16 * i) * LDA + ks, LDA);
                wmma::load_matrix_sync(al[i], sAl + (wm + 16 * i) * LDA + ks, LDA);
            }
#pragma unroll
            for (int j = 0; j < 4; j++) {
                wmma::fragment<wmma::matrix_b, 16, 16, 16, bf16, wmma::col_major> bh, bl;
                wmma::load_matrix_sync(bh, sBh + (wn + 16 * j) * LDA + ks, LDA);
                wmma::load_matrix_sync(bl, sBl + (wn + 16 * j) * LDA + ks, LDA);
#pragma unroll
                for (int i = 0; i < 2; i++) {
                    wmma::mma_sync(acc[i][j], al[i], bh, acc[i][j]);
                    wmma::mma_sync(acc[i][j], ah[i], bl, acc[i][j]);
                    wmma::mma_sync(acc[i][j], ah[i], bh, acc[i][j]);
                }
            }
        }
        __syncthreads();
    }

    if constexpr (EPI == 0) {
        float* pc = C + cOff;
#pragma unroll
        for (int i = 0; i < 2; i++)
#pragma unroll
            for (int j = 0; j < 4; j++)
                wmma::store_matrix_sync(
                    pc + (long long)(m0 + wm + 16 * i) * ldc + n0 + wn + 16 * j,
                    acc[i][j], ldc, wmma::mem_row_major);
    } else {
        float* cst = (float*)smem;
#pragma unroll
        for (int i = 0; i < 2; i++)
#pragma unroll
            for (int j = 0; j < 4; j++)
                wmma::store_matrix_sync(cst + (wm + 16 * i) * CPITCH + wn + 16 * j,
                                        acc[i][j], CPITCH, wmma::mem_row_major);
        __syncthreads();
        const int row = tid >> 1, cb = (tid & 1) * 64;
        bf16* ph_ = Chi + cOff + (long long)(m0 + row) * ldc + n0 + cb;
        bf16* pl_ = Clo + cOff + (long long)(m0 + row) * ldc + n0 + cb;
        const float* src = cst + row * CPITCH + cb;
#pragma unroll
        for (int i = 0; i < 32; i++) {
            float a0 = src[2 * i], a1 = src[2 * i + 1];
            bf162 hh, ll;
            hh.x = __float2bfloat16(a0);
            ll.x = __float2bfloat16(a0 - __bfloat162float(hh.x));
            hh.y = __float2bfloat16(a1);
            ll.y = __float2bfloat16(a1 - __bfloat162float(hh.y));
            reinterpret_cast<bf162*>(ph_)[i] = hh;
            reinterpret_cast<bf162*>(pl_)[i] = ll;
        }
    }
}

// ---------------- fused input split: all 5 tensors in one launch -------------
__device__ __forceinline__ void split4(float4 v, bf16* __restrict__ hi,
                                       bf16* __restrict__ lo, int i) {
    bf162 h0, h1, l0, l1;
    h0.x = __float2bfloat16(v.x); l0.x = __float2bfloat16(v.x - __bfloat162float(h0.x));
    h0.y = __float2bfloat16(v.y); l0.y = __float2bfloat16(v.y - __bfloat162float(h0.y));
    h1.x = __float2bfloat16(v.z); l1.x = __float2bfloat16(v.z - __bfloat162float(h1.x));
    h1.y = __float2bfloat16(v.w); l1.y = __float2bfloat16(v.w - __bfloat162float(h1.y));
    reinterpret_cast<bf162*>(hi)[2 * i]     = h0;
    reinterpret_cast<bf162*>(hi)[2 * i + 1] = h1;
    reinterpret_cast<bf162*>(lo)[2 * i]     = l0;
    reinterpret_cast<bf162*>(lo)[2 * i + 1] = l1;
}

constexpr int F4_X  = MROWS * HID / 4;              // 524288
constexpr int F4_QW = Hh * Dd * HID / 4;            // 1048576
constexpr int F4_KW = KVh * Dd * HID / 4;           // 524288
constexpr int F4_TOT = F4_X + F4_QW + 2 * F4_KW + (HID * Hh * Dd / 4);

__global__ void k_split_all(const float* __restrict__ x, const float* __restrict__ qw,
                            const float* __restrict__ kw, const float* __restrict__ vw,
                            const float* __restrict__ ow) {
    int i = blockIdx.x * 256 + threadIdx.x;
    if (i >= F4_TOT) return;
    if (i < F4_X) {
        split4(((const float4*)x)[i], g_xh, g_xl, i);
    } else if (i < F4_X + F4_QW) {
        int j = i - F4_X;
        split4(((const float4*)qw)[j], g_wh, g_wl, j);
    } else if (i < F4_X + F4_QW + F4_KW) {
        int j = i - (F4_X + F4_QW);
        split4(((const float4*)kw)[j], g_wh + Hh * Dd * HID, g_wl + Hh * Dd * HID, j);
    } else if (i < F4_X + F4_QW + 2 * F4_KW) {
        int j = i - (F4_X + F4_QW + F4_KW);
        split4(((const float4*)vw)[j], g_wh + (Hh + KVh) * Dd * HID,
               g_wl + (Hh + KVh) * Dd * HID, j);
    } else {
        int j = i - (F4_X + F4_QW + 2 * F4_KW);
        split4(((const float4*)ow)[j], g_owh, g_owl, j);
    }
}

// ---------------- QKV post: RMSNorm + RoPE + bf16 split ----------------
__global__ void k_qkvpost(const float* __restrict__ qkv, const float* __restrict__ pe,
                          const float* __restrict__ qnw, const float* __restrict__ knw,
                          bf16* __restrict__ qh, bf16* __restrict__ ql,
                          bf16* __restrict__ kh, bf16* __restrict__ kl,
                          bf16* __restrict__ vh, bf16* __restrict__ vl) {
    const int task = blockIdx.x * 4 + (threadIdx.x >> 5);
    const int lane = threadIdx.x & 31;

    if (task < 65536) {  // Q
        const int bs = task >> 4, h = task & 15;
        const float* src = qkv + (long long)bs * NQKV + h * Dd;
        float x0 = src[lane], x1 = src[lane + 32], x2 = src[lane + 64], x3 = src[lane + 96];
        float ss = x0 * x0 + x1 * x1 + x2 * x2 + x3 * x3;
#pragma unroll
        for (int o = 16; o; o >>= 1) ss += __shfl_xor_sync(0xffffffffu, ss, o);
        float inv = rsqrtf(ss * (1.0f / 128.0f) + 1e-6f);
        float n0 = x0 * inv * qnw[lane],      n1 = x1 * inv * qnw[lane + 32];
        float n2 = x2 * inv * qnw[lane + 64], n3 = x3 * inv * qnw[lane + 96];
        const float* per = pe + (long long)bs * Dd;
        float c0 = per[lane],      s0 = per[64 + lane];
        float c1 = per[32 + lane], s1 = per[96 + lane];
        float o0 = (n0 * c0 - n2 * s0) * SCALE_Q;
        float o1 = (n1 * c1 - n3 * s1) * SCALE_Q;
        float o2 = (n0 * s0 + n2 * c0) * SCALE_Q;
        float o3 = (n1 * s1 + n3 * c1) * SCALE_Q;
        const int b = bs >> 11, s = bs & 2047;
        long long base = ((long long)(b * Hh + h) * Ss + s) * Dd;
        wsb(qh, ql, base + lane, o0);       wsb(qh, ql, base + lane + 32, o1);
        wsb(qh, ql, base + lane + 64, o2);  wsb(qh, ql, base + lane + 96, o3);
    } else if (task < 98304) {  // K
        const int t = task - 65536;
        const int bs = t >> 3, kvh = t & 7;
        const float* src = qkv + (long long)bs * NQKV + Hh * Dd + kvh * Dd;
        float x0 = src[lane], x1 = src[lane + 32], x2 = src[lane + 64], x3 = src[lane + 96];
        float ss = x0 * x0 + x1 * x1 + x2 * x2 + x3 * x3;
#pragma unroll
        for (int o = 16; o; o >>= 1) ss += __shfl_xor_sync(0xffffffffu, ss, o);
        float inv = rsqrtf(ss * (1.0f / 128.0f) + 1e-6f);
        float n0 = x0 * inv * knw[lane],      n1 = x1 * inv * knw[lane + 32];
        float n2 = x2 * inv * knw[lane + 64], n3 = x3 * inv * knw[lane + 96];
        const float* per = pe + (long long)bs * Dd;
        float c0 = per[lane],      s0 = per[64 + lane];
        float c1 = per[32 + lane], s1 = per[96 + lane];
        float o0 = n0 * c0 - n2 * s0, o1 = n1 * c1 - n3 * s1;
        float o2 = n0 * s0 + n2 * c0, o3 = n1 * s1 + n3 * c1;
        const int b = bs >> 11, s = bs & 2047;
        long long base = ((long long)(b * KVh + kvh) * Ss + s) * Dd;
        wsb(kh, kl, base + lane, o0);       wsb(kh, kl, base + lane + 32, o1);
        wsb(kh, kl, base + lane + 64, o2);  wsb(kh, kl, base + lane + 96, o3);
    } else {  // V
        const int t = task - 98304;
        const int bs = t >> 3, kvh = t & 7;
        const float* src = qkv + (long long)bs * NQKV + (Hh + KVh) * Dd + kvh * Dd;
        const int b = bs >> 11, s = bs & 2047;
        long long base = ((long long)(b * KVh + kvh) * Ss + s) * Dd;
        wsb(vh, vl, base + lane,      src[lane]);
        wsb(vh, vl, base + lane + 32, src[lane + 32]);
        wsb(vh, vl, base + lane + 64, src[lane + 64]);
        wsb(vh, vl, base + lane + 96, src[lane + 96]);
    }
}

// ---------------- V transpose: [B,KV,S,D] -> [B,KV,D,S] (hi+lo) ----------------
__global__ void k_vt(const bf16* __restrict__ vh, const bf16* __restrict__ vl,
                     bf16* __restrict__ vth, bf16* __restrict__ vtl) {
    __shared__ bf16 th[32][33], tl[32][33];
    const int bz = blockIdx.z;
    const long long base = (long long)bz * Ss * Dd;
    const int s0 = blockIdx.x * 32, d0 = blockIdx.y * 32;
    const int tx = threadIdx.x, ty = threadIdx.y;
#pragma unroll
    for (int j = 0; j < 4; j++) {
        int r = ty + j * 8;
        th[r][tx] = vh[base + (long long)(s0 + r) * Dd + d0 + tx];
        tl[r][tx] = vl[base + (long long)(s0 + r) * Dd + d0 + tx];
    }
    __syncthreads();
#pragma unroll
    for (int j = 0; j < 4; j++) {
        int r = ty + j * 8;
        vth[base + (long long)(d0 + r) * Ss + s0 + tx] = th[tx][r];
        vtl[base + (long long)(d0 + r) * Ss + s0 + tx] = tl[tx][r];
    }
}

// ---------------- causal softmax: vectorized (float2 in, bf162 out) ----------
__global__ void k_softmax(const float* __restrict__ sc, bf16* __restrict__ ph,
                          bf16* __restrict__ pl) {
    const int row = blockIdx.x;           // [0, B*H*S)
    const int s = row & (Ss - 1);
    const float* p = sc + (long long)row * Ss;
    bf16* oh = ph + (long long)row * Ss;
    bf16* ol = pl + (long long)row * Ss;
    const int L = s + 1;
    const int tid = threadIdx.x;
    const int base = tid * 2;

    float2 ev[8];
    int cnt = 0;
    float mx = -3.4e38f;
    float tailv = 0.0f;
    bool hasTail = false;
    int i = base;
    for (; i + 1 < L; i += 256) {
        float2 v = *(const float2*)(p + i);
        ev[cnt++] = v;
        mx = fmaxf(mx, fmaxf(v.x, v.y));
    }
    if (i < L) { tailv = p[i]; hasTail = true; mx = fmaxf(mx, tailv); }

#pragma unroll
    for (int o = 16; o; o >>= 1) mx = fmaxf(mx, __shfl_xor_sync(0xffffffffu, mx, o));
    __shared__ float shm[4], shs[4];
    if ((tid & 31) == 0) shm[tid >> 5] = mx;
    __syncthreads();
    mx = fmaxf(fmaxf(shm[0], shm[1]), fmaxf(shm[2], shm[3]));

    float sum = 0.0f;
    for (int j = 0; j < cnt; j++) {
        float2 e;
        e.x = __expf(ev[j].x - mx);
        e.y = __expf(ev[j].y - mx);
        ev[j] = e;
        sum += e.x + e.y;
    }
    if (hasTail) { tailv = __expf(tailv - mx); sum += tailv; }
#pragma unroll
    for (int o = 16; o; o >>= 1) sum += __shfl_xor_sync(0xffffffffu, sum, o);
    if ((tid & 31) == 0) shs[tid >> 5] = sum;
    __syncthreads();
    sum = shs[0] + shs[1] + shs[2] + shs[3];
    const float inv = 1.0f / sum;

    i = base;
    for (int j = 0; j < cnt; j++, i += 256) {
        float v0 = ev[j].x * inv, v1 = ev[j].y * inv;
        bf162 hh, ll;
        hh.x = __float2bfloat16(v0);
        ll.x = __float2bfloat16(v0 - __bfloat162float(hh.x));
        hh.y = __float2bfloat16(v1);
        ll.y = __float2bfloat16(v1 - __bfloat162float(hh.y));
        *(bf162*)(oh + i) = hh;
        *(bf162*)(ol + i) = ll;
    }
    if (hasTail) {
        float v = tailv * inv;
        bf16 h = __float2bfloat16(v);
        oh[i] = h;
        ol[i] = __float2bfloat16(v - __bfloat162float(h));
    }
    const int tileEnd = ((s >> 7) << 7) + 128;  // pad to 128-tile boundary for AV
    bf16 z = __float2bfloat16(0.0f);
    for (int j = L + tid; j < tileEnd; j += 128) { oh[j] = z; ol[j] = z; }
}

// ---------------- launch -----------------------------------------------------
extern "C" void kernel_launch(void* const* d_in, const int* in_sizes, int n_in,
                              void* d_out, int out_size) {
    (void)in_sizes; (void)n_in; (void)out_size;
    const float* x   = (const float*)d_in[0];
    const float* pe  = (const float*)d_in[1];
    const float* qw  = (const float*)d_in[2];
    const float* kw  = (const float*)d_in[3];
    const float* vw  = (const float*)d_in[4];
    const float* ow  = (const float*)d_in[5];
    const float* qnw = (const float*)d_in[6];
    const float* knw = (const float*)d_in[7];
    float* out = (float*)d_out;

    bf16 *xh, *xl, *wh, *wl, *owh, *owl;
    bf16 *qh, *ql, *kh, *kl, *vh, *vl, *vth, *vtl, *ph, *pl, *aoh, *aol;
    float *qkvp, *sc;
    cudaGetSymbolAddress((void**)&xh, g_xh);   cudaGetSymbolAddress((void**)&xl, g_xl);
    cudaGetSymbolAddress((void**)&wh, g_wh);   cudaGetSymbolAddress((void**)&wl, g_wl);
    cudaGetSymbolAddress((void**)&owh, g_owh); cudaGetSymbolAddress((void**)&owl, g_owl);
    cudaGetSymbolAddress((void**)&qkvp, g_qkv);
    cudaGetSymbolAddress((void**)&qh, g_qh);   cudaGetSymbolAddress((void**)&ql, g_ql);
    cudaGetSymbolAddress((void**)&kh, g_kh);   cudaGetSymbolAddress((void**)&kl, g_kl);
    cudaGetSymbolAddress((void**)&vh, g_vh);   cudaGetSymbolAddress((void**)&vl, g_vl);
    cudaGetSymbolAddress((void**)&vth, g_vth); cudaGetSymbolAddress((void**)&vtl, g_vtl);
    cudaGetSymbolAddress((void**)&sc, g_sc);
    cudaGetSymbolAddress((void**)&ph, g_ph);   cudaGetSymbolAddress((void**)&pl, g_pl);
    cudaGetSymbolAddress((void**)&aoh, g_aoh); cudaGetSymbolAddress((void**)&aol, g_aol);

    cudaFuncSetAttribute(k_mm<0>, cudaFuncAttributeMaxDynamicSharedMemorySize, SMEM_MM);
    cudaFuncSetAttribute(k_mm<1>, cudaFuncAttributeMaxDynamicSharedMemorySize, SMEM_MM);

    // 1) bf16 splits of x and all weights (single launch)
    k_split_all<<<(F4_TOT + 255) / 256, 256>>>(x, qw, kw, vw, ow);

    // 2) QKV projection: [4096,2048] @ [4096,2048]^T -> g_qkv [4096,4096] fp32
    {
        dim3 g(NQKV / 128, MROWS / 128, 1);
        k_mm<0><<<g, 256, SMEM_MM>>>(xh, xl, wh, wl, qkvp, nullptr, nullptr,
                                     HID, NQKV, 0, 0, 0, 0, 0, 0, 1, 1, 0);
    }

    // 3) RMSNorm + RoPE + bf16 split -> q/k/v [B,(KV)H,S,D]
    k_qkvpost<<<32768, 128>>>(qkvp, pe, qnw, knw, qh, ql, kh, kl, vh, vl);

    // 4) V transpose -> [B,KV,D,S]
    {
        dim3 g(Ss / 32, Dd / 32, Bz * KVh);
        k_vt<<<g, dim3(32, 8)>>>(vh, vl, vth, vtl);
    }

    // 5) scores = q @ k^T (causal tile-skip) -> g_sc fp32 [B,H,S,S]
    {
        dim3 g(Ss / 128, Ss / 128, Bz * Hh);
        k_mm<0><<<g, 256, SMEM_MM>>>(
            qh, ql, kh, kl, sc, nullptr, nullptr, Dd, Ss,
            (long long)Hh * Ss * Dd, (long long)Ss * Dd,
            (long long)KVh * Ss * Dd, (long long)Ss * Dd,
            (long long)Hh * Ss * Ss, (long long)Ss * Ss,
            Hh, Hh / KVh, 1);
    }

    // 6) softmax -> P bf16 hi/lo, zero-padded to tile edge (vectorized)
    k_softmax<<<Bz * Hh * Ss, 128>>>(sc, ph, pl);

    // 7) attnout = P @ V^T (K-trimmed), bf16 hi/lo out [B,S,H,D]
    {
        dim3 g(1, Ss / 128, Bz * Hh);
        k_mm<1><<<g, 256, SMEM_MM>>>(
            ph, pl, vth, vtl, nullptr, aoh, aol, Ss, Hh * Dd,
            (long long)Hh * Ss * Ss, (long long)Ss * Ss,
            (long long)KVh * Dd * Ss, (long long)Dd * Ss,
            (long long)Ss * Hh * Dd, (long long)Dd,
            Hh, Hh / KVh, 2);
    }

    // 8) out = attnout @ o_w^T -> d_out [4096,2048] fp32
    {
        dim3 g(HID / 128, MROWS / 128, 1);
        k_mm<0><<<g, 256, SMEM_MM>>>(aoh, aol, owh, owl, out, nullptr, nullptr,
                                     Hh * Dd, HID, 0, 0, 0, 0, 0, 0, 1, 1, 0);
    }
}

// round 14
// speedup vs baseline: 1.5068x; 1.0015x over previous
#include <cuda_runtime.h>
#include <cuda_bf16.h>
#include <mma.h>
#include <cstdint>

using namespace nvcuda;
typedef __nv_bfloat16 bf16;
typedef __nv_bfloat162 bf162;

// ---------------- problem constants ----------------
constexpr int Bz  = 2;
constexpr int Ss  = 2048;
constexpr int HID = 2048;
constexpr int Hh  = 16;
constexpr int KVh = 8;
constexpr int Dd  = 128;
constexpr int MROWS = Bz * Ss;                 // 4096
constexpr int NQKV  = (Hh + 2 * KVh) * Dd;     // 4096
constexpr float SCALE_Q = 0.08838834764831845f; // 1/sqrt(128)

// ---------------- scratch (static device memory) ----------------
__device__ bf16 g_xh[MROWS * HID], g_xl[MROWS * HID];
__device__ bf16 g_wh[NQKV * HID],  g_wl[NQKV * HID];
__device__ bf16 g_owh[HID * Hh * Dd], g_owl[HID * Hh * Dd];
__device__ float g_qkv[(size_t)MROWS * NQKV];
constexpr size_t QN = (size_t)Bz * Hh * Ss * Dd;
constexpr size_t KN = (size_t)Bz * KVh * Ss * Dd;
__device__ bf16 g_qh[QN], g_ql[QN];
__device__ bf16 g_kh[KN], g_kl[KN];
__device__ bf16 g_vh[KN], g_vl[KN];
__device__ bf16 g_vth[KN], g_vtl[KN];          // V transposed [B,KV,D,S]
constexpr size_t SCN = (size_t)Bz * Hh * Ss * Ss;
__device__ float g_sc[SCN];
constexpr size_t NROW = (size_t)Bz * Hh * Ss;  // 65536 attention rows
__device__ float g_pm[NROW * 16], g_ps[NROW * 16];  // per-(row,tile) max / sumexp
__device__ float g_sm[NROW], g_si[NROW];            // final per-row max / 1/sum
__device__ bf16 g_aoh[(size_t)MROWS * Hh * Dd], g_aol[(size_t)MROWS * Hh * Dd];

// ---------------- helpers ----------------
__device__ __forceinline__ uint32_t s2u(const void* p) {
    uint32_t a;
    asm("{ .reg .u64 t; cvta.to.shared.u64 t, %1; cvt.u32.u64 %0, t; }" : "=r"(a) : "l"(p));
    return a;
}
__device__ __forceinline__ void cpa16(uint32_t dst, const void* src) {
    asm volatile("cp.async.cg.shared.global [%0], [%1], 16;" :: "r"(dst), "l"(src) : "memory");
}
#define CP_COMMIT() asm volatile("cp.async.commit_group;" ::: "memory")
#define CP_WAIT(n)  asm volatile("cp.async.wait_group %0;" :: "n"(n) : "memory")

__device__ __forceinline__ void wsb(bf16* __restrict__ hi, bf16* __restrict__ lo,
                                    long long i, float v) {
    bf16 h = __float2bfloat16(v);
    hi[i] = h;
    lo[i] = __float2bfloat16(v - __bfloat162float(h));
}

// ---------------- HMMA bf16-split batched GEMM ----------------
// C[m,n] = sum_k A[m,k]*B[n,k], 3 terms: Ah*Bh + Al*Bh + Ah*Bl.
// CTA tile 128x128, K-chunk 32, cp.async x2 buf, LDA=40, 2 CTAs/SM.
// EPI 0: fp32 C.  EPI 1: bf16 split Chi/Clo.
// EPI 3: fp32 C + per-(row,tile) softmax stats (causally masked) -> Mp/Sp.
// CONV: A operand built on the fly from fp32 scores SCF + final stats Mst/Ist
//       (exp -> fp32 hi/lo split -> STS); A cp.async skipped.
// causal 0: none; 1: skip n0>m0; 2: Kend = m0+128.
constexpr int LDA   = 40;
constexpr int MATB  = 128 * LDA * 2;          // 10240 B per matrix tile
constexpr int STAGE = 4 * MATB;               // 40960 B
constexpr int SMEM_MM = 2 * STAGE;            // 81920 B
constexpr int CPITCH = 132;                   // fp32 staging pitch; mult of 4 (wmma)

template <int EPI, bool CONV>
__global__ __launch_bounds__(256, 2) void k_mm(
    const bf16* __restrict__ Ah, const bf16* __restrict__ Al,
    const bf16* __restrict__ Bh, const bf16* __restrict__ Bl,
    float* __restrict__ C, bf16* __restrict__ Chi, bf16* __restrict__ Clo,
    int K, int ldc,
    long long aSB, long long aSH, long long bSB, long long bSH,
    long long cSB, long long cSH, int Hdim, int gqa, int causal,
    const float* __restrict__ SCF, const float* __restrict__ Mst,
    const float* __restrict__ Ist, float* __restrict__ Mp, float* __restrict__ Sp) {
    const int m0 = blockIdx.y * 128, n0 = blockIdx.x * 128;
    if (causal == 1 && n0 > m0) return;

    extern __shared__ __align__(16) char smem[];
    const uint32_t sb = s2u(smem);
    const int tid = threadIdx.x, wid = tid >> 5;

    const int z = blockIdx.z, b = z / Hdim, h = z - b * Hdim;
    const bf16* pAh = Ah + (long long)b * aSB + (long long)h * aSH;
    const bf16* pAl = Al + (long long)b * aSB + (long long)h * aSH;
    const bf16* pBh = Bh + (long long)b * bSB + (long long)(h / gqa) * bSH;
    const bf16* pBl = Bl + (long long)b * bSB + (long long)(h / gqa) * bSH;
    const long long cOff = (long long)b * cSB + (long long)h * cSH;

    uint32_t sdst[2];
    long long offA[2];
    const long long dBA = (long long)(n0 - m0) * K;
#pragma unroll
    for (int i = 0; i < 2; i++) {
        int idx = i * 256 + tid, r = idx >> 2, c8 = (idx & 3) << 3;
        sdst[i] = (uint32_t)(r * (LDA * 2) + c8 * 2);
        offA[i] = (long long)(m0 + r) * K + c8;
    }

    const int Kend = (causal == 2) ? (m0 + 128) : K;
    const int nch = Kend >> 5;

    auto loadChunk = [&](int c, int st) {
        const uint32_t base = sb + st * STAGE;
        const long long kb = (long long)c * 32;
#pragma unroll
        for (int i = 0; i < 2; i++) {
            const long long oa = offA[i] + kb, ob = oa + dBA;
            if constexpr (!CONV) {
                cpa16(base + sdst[i],        pAh + oa);
                cpa16(base + MATB + sdst[i], pAl + oa);
            }
            cpa16(base + 2 * MATB + sdst[i], pBh + ob);
            cpa16(base + 3 * MATB + sdst[i], pBl + ob);
        }
        CP_COMMIT();
    };

    // CONV setup: per-thread P conversion slot (pair of threads per row)
    const int crow = tid >> 1, cc16 = (tid & 1) * 16;
    float cm = 0.0f, ci = 0.0f;
    const float* csrc = nullptr;
    int Lrow = 0;
    if constexpr (CONV) {
        const long long zr = (long long)z * Ss + m0 + crow;
        cm = Mst[zr];
        ci = Ist[zr];
        csrc = SCF + (long long)z * Ss * Ss + (long long)(m0 + crow) * Ss + cc16;
        Lrow = m0 + crow;
    }

    const int wm = (wid & 3) * 32;
    const int wn = (wid >> 2) * 64;

    wmma::fragment<wmma::accumulator, 16, 16, 16, float> acc[2][4];
#pragma unroll
    for (int i = 0; i < 2; i++)
#pragma unroll
        for (int j = 0; j < 4; j++) wmma::fill_fragment(acc[i][j], 0.0f);

    loadChunk(0, 0);
    for (int c = 0; c < nch; c++) {
        if (c + 1 < nch) { loadChunk(c + 1, (c + 1) & 1); CP_WAIT(1); }
        else             { CP_WAIT(0); }
        if constexpr (CONV) {
            const float4* p4 = (const float4*)(csrc + c * 32);
            float4 a0 = p4[0], a1 = p4[1], a2 = p4[2], a3 = p4[3];
            float v[16] = { a0.x, a0.y, a0.z, a0.w, a1.x, a1.y, a1.z, a1.w,
                            a2.x, a2.y, a2.z, a2.w, a3.x, a3.y, a3.z, a3.w };
            bf16* dAh = (bf16*)(smem + (c & 1) * STAGE) + crow * LDA + cc16;
            bf16* dAl = (bf16*)(smem + (c & 1) * STAGE + MATB) + crow * LDA + cc16;
            const int jb = c * 32 + cc16;
#pragma unroll
            for (int i = 0; i < 16; i += 2) {
                float p0 = (jb + i     <= Lrow) ? __expf(v[i]     - cm) * ci : 0.0f;
                float p1 = (jb + i + 1 <= Lrow) ? __expf(v[i + 1] - cm) * ci : 0.0f;
                bf162 hh, ll;
                hh.x = __float2bfloat16(p0);
                ll.x = __float2bfloat16(p0 - __bfloat162float(hh.x));
                hh.y = __float2bfloat16(p1);
                ll.y = __float2bfloat16(p1 - __bfloat162float(hh.y));
                *(bf162*)(dAh + i) = hh;
                *(bf162*)(dAl + i) = ll;
            }
        }
        __syncthreads();

        const char* st = smem + (c & 1) * STAGE;
        const bf16* sAh = (const bf16*)(st);
        const bf16* sAl = (const bf16*)(st + MATB);
        const bf16* sBh = (const bf16*)(st + 2 * MATB);
        const bf16* sBl = (const bf16*)(st + 3 * MATB);

#pragma unroll
        for (int ks = 0; ks < 32; ks += 16) {
            wmma::fragment<wmma::matrix_a, 16, 16, 16, bf16, wmma::row_major> ah[2], al[2];
#pragma unroll
            for (int i = 0; i < 2; i++) {
                wmma::load_matrix_sync(ah[i], sAh + (wm + 16 * i) * LDA + ks, LDA);
                wmma::load_matrix_sync(al[i], sAl + (wm + 16 * i) * LDA + ks, LDA);
            }
#pragma unroll
            for (int j = 0; j < 4; j++) {
                wmma::fragment<wmma::matrix_b, 16, 16, 16, bf16, wmma::col_major> bh, bl;
                wmma::load_matrix_sync(bh, sBh + (wn + 16 * j) * LDA + ks, LDA);
                wmma::load_matrix_sync(bl, sBl + (wn + 16 * j) * LDA + ks, LDA);
#pragma unroll
                for (int i = 0; i < 2; i++) {
                    wmma::mma_sync(acc[i][j], al[i], bh, acc[i][j]);
                    wmma::mma_sync(acc[i][j], ah[i], bl, acc[i][j]);
                    wmma::mma_sync(acc[i][j], ah[i], bh, acc[i][j]);
                }
            }
        }
        __syncthreads();
    }

    if constexpr (EPI == 0) {
        float* pc = C + cOff;
#pragma unroll
        for (int i = 0; i < 2; i++)
#pragma unroll
            for (int j = 0; j < 4; j++)
                wmma::store_matrix_sync(
                    pc + (long long)(m0 + wm + 16 * i) * ldc + n0 + wn + 16 * j,
                    acc[i][j], ldc, wmma::mem_row_major);
    } else if constexpr (EPI == 1) {
        float* cst = (float*)smem;
#pragma unroll
        for (int i = 0; i < 2; i++)
#pragma unroll
            for (int j = 0; j < 4; j++)
                wmma::store_matrix_sync(cst + (wm + 16 * i) * CPITCH + wn + 16 * j,
                                        acc[i][j], CPITCH, wmma::mem_row_major);
        __syncthreads();
        const int row = tid >> 1, cb = (tid & 1) * 64;
        bf16* ph_ = Chi + cOff + (long long)(m0 + row) * ldc + n0 + cb;
        bf16* pl_ = Clo + cOff + (long long)(m0 + row) * ldc + n0 + cb;
        const float* src = cst + row * CPITCH + cb;
#pragma unroll
        for (int i = 0; i < 32; i++) {
            float a0 = src[2 * i], a1 = src[2 * i + 1];
            bf162 hh, ll;
            hh.x = __float2bfloat16(a0);
            ll.x = __float2bfloat16(a0 - __bfloat162float(hh.x));
            hh.y = __float2bfloat16(a1);
            ll.y = __float2bfloat16(a1 - __bfloat162float(hh.y));
            reinterpret_cast<bf162*>(ph_)[i] = hh;
            reinterpret_cast<bf162*>(pl_)[i] = ll;
        }
    } else {  // EPI == 3: scores + per-tile softmax stats
        float* cst = (float*)smem;
#pragma unroll
        for (int i = 0; i < 2; i++)
#pragma unroll
            for (int j = 0; j < 4; j++)
                wmma::store_matrix_sync(cst + (wm + 16 * i) * CPITCH + wn + 16 * j,
                                        acc[i][j], CPITCH, wmma::mem_row_major);
        __syncthreads();
        const int row = tid >> 1, cb = (tid & 1) * 64;
        const float* src = cst + row * CPITCH + cb;
        float* pc = C + cOff + (long long)(m0 + row) * ldc + n0 + cb;
#pragma unroll
        for (int i = 0; i < 16; i++)
            reinterpret_cast<float4*>(pc)[i] = reinterpret_cast<const float4*>(src)[i];
        // causal-masked per-tile stats for this row-half, combined across pair
        const int nv = (n0 == m0) ? min(64, row - cb + 1) : 64;
        float mx = -3.4e38f;
        for (int i = 0; i < nv; i++) mx = fmaxf(mx, src[i]);
        float M = fmaxf(mx, __shfl_xor_sync(0xffffffffu, mx, 1));
        float sum = 0.0f;
        for (int i = 0; i < nv; i++) sum += __expf(src[i] - M);
        sum += __shfl_xor_sync(0xffffffffu, sum, 1);
        if ((tid & 1) == 0) {
            const long long ri = ((long long)z * Ss + m0 + row) * 16 + (n0 >> 7);
            Mp[ri] = M;
            Sp[ri] = sum;
        }
    }
}

// ---------------- stats reduce: per-row (max, 1/sum) from per-tile stats -----
__global__ void k_sred(const float* __restrict__ Mp, const float* __restrict__ Sp,
                       float* __restrict__ Mf, float* __restrict__ If) {
    const int idx = blockIdx.x * 256 + threadIdx.x;
    if (idx >= (int)NROW) return;
    const int srow = idx & (Ss - 1);
    const int nt = (srow >> 7) + 1;
    const float* mp = Mp + (long long)idx * 16;
    const float* sp = Sp + (long long)idx * 16;
    float M = -3.4e38f;
    for (int t = 0; t < nt; t++) M = fmaxf(M, mp[t]);
    float S = 0.0f;
    for (int t = 0; t < nt; t++) S += sp[t] * __expf(mp[t] - M);
    Mf[idx] = M;
    If[idx] = 1.0f / S;
}

// ---------------- fused input split: all 5 tensors in one launch -------------
__device__ __forceinline__ void split4(float4 v, bf16* __restrict__ hi,
                                       bf16* __restrict__ lo, int i) {
    bf162 h0, h1, l0, l1;
    h0.x = __float2bfloat16(v.x); l0.x = __float2bfloat16(v.x - __bfloat162float(h0.x));
    h0.y = __float2bfloat16(v.y); l0.y = __float2bfloat16(v.y - __bfloat162float(h0.y));
    h1.x = __float2bfloat16(v.z); l1.x = __float2bfloat16(v.z - __bfloat162float(h1.x));
    h1.y = __float2bfloat16(v.w); l1.y = __float2bfloat16(v.w - __bfloat162float(h1.y));
    reinterpret_cast<bf162*>(hi)[2 * i]     = h0;
    reinterpret_cast<bf162*>(hi)[2 * i + 1] = h1;
    reinterpret_cast<bf162*>(lo)[2 * i]     = l0;
    reinterpret_cast<bf162*>(lo)[2 * i + 1] = l1;
}

constexpr int F4_X  = MROWS * HID / 4;
constexpr int F4_QW = Hh * Dd * HID / 4;
constexpr int F4_KW = KVh * Dd * HID / 4;
constexpr int F4_TOT = F4_X + F4_QW + 2 * F4_KW + (HID * Hh * Dd / 4);

__global__ void k_split_all(const float* __restrict__ x, const float* __restrict__ qw,
                            const float* __restrict__ kw, const float* __restrict__ vw,
                            const float* __restrict__ ow) {
    int i = blockIdx.x * 256 + threadIdx.x;
    if (i >= F4_TOT) return;
    if (i < F4_X) {
        split4(((const float4*)x)[i], g_xh, g_xl, i);
    } else if (i < F4_X + F4_QW) {
        int j = i - F4_X;
        split4(((const float4*)qw)[j], g_wh, g_wl, j);
    } else if (i < F4_X + F4_QW + F4_KW) {
        int j = i - (F4_X + F4_QW);
        split4(((const float4*)kw)[j], g_wh + Hh * Dd * HID, g_wl + Hh * Dd * HID, j);
    } else if (i < F4_X + F4_QW + 2 * F4_KW) {
        int j = i - (F4_X + F4_QW + F4_KW);
        split4(((const float4*)vw)[j], g_wh + (Hh + KVh) * Dd * HID,
               g_wl + (Hh + KVh) * Dd * HID, j);
    } else {
        int j = i - (F4_X + F4_QW + 2 * F4_KW);
        split4(((const float4*)ow)[j], g_owh, g_owl, j);
    }
}

// ---------------- QKV post: RMSNorm + RoPE + bf16 split ----------------
__global__ void k_qkvpost(const float* __restrict__ qkv, const float* __restrict__ pe,
                          const float* __restrict__ qnw, const float* __restrict__ knw,
                          bf16* __restrict__ qh, bf16* __restrict__ ql,
                          bf16* __restrict__ kh, bf16* __restrict__ kl,
                          bf16* __restrict__ vh, bf16* __restrict__ vl) {
    const int task = blockIdx.x * 4 + (threadIdx.x >> 5);
    const int lane = threadIdx.x & 31;

    if (task < 65536) {  // Q
        const int bs = task >> 4, h = task & 15;
        const float* src = qkv + (long long)bs * NQKV + h * Dd;
        float x0 = src[lane], x1 = src[lane + 32], x2 = src[lane + 64], x3 = src[lane + 96];
        float ss = x0 * x0 + x1 * x1 + x2 * x2 + x3 * x3;
#pragma unroll
        for (int o = 16; o; o >>= 1) ss += __shfl_xor_sync(0xffffffffu, ss, o);
        float inv = rsqrtf(ss * (1.0f / 128.0f) + 1e-6f);
        float n0 = x0 * inv * qnw[lane],      n1 = x1 * inv * qnw[lane + 32];
        float n2 = x2 * inv * qnw[lane + 64], n3 = x3 * inv * qnw[lane + 96];
        const float* per = pe + (long long)bs * Dd;
        float c0 = per[lane],      s0 = per[64 + lane];
        float c1 = per[32 + lane], s1 = per[96 + lane];
        float o0 = (n0 * c0 - n2 * s0) * SCALE_Q;
        float o1 = (n1 * c1 - n3 * s1) * SCALE_Q;
        float o2 = (n0 * s0 + n2 * c0) * SCALE_Q;
        float o3 = (n1 * s1 + n3 * c1) * SCALE_Q;
        const int b = bs >> 11, s = bs & 2047;
        long long base = ((long long)(b * Hh + h) * Ss + s) * Dd;
        wsb(qh, ql, base + lane, o0);       wsb(qh, ql, base + lane + 32, o1);
        wsb(qh, ql, base + lane + 64, o2);  wsb(qh, ql, base + lane + 96, o3);
    } else if (task < 98304) {  // K
        const int t = task - 65536;
        const int bs = t >> 3, kvh = t & 7;
        const float* src = qkv + (long long)bs * NQKV + Hh * Dd + kvh * Dd;
        float x0 = src[lane], x1 = src[lane + 32], x2 = src[lane + 64], x3 = src[lane + 96];
        float ss = x0 * x0 + x1 * x1 + x2 * x2 + x3 * x3;
#pragma unroll
        for (int o = 16; o; o >>= 1) ss += __shfl_xor_sync(0xffffffffu, ss, o);
        float inv = rsqrtf(ss * (1.0f / 128.0f) + 1e-6f);
        float n0 = x0 * inv * knw[lane],      n1 = x1 * inv * knw[lane + 32];
        float n2 = x2 * inv * knw[lane + 64], n3 = x3 * inv * knw[lane + 96];
        const float* per = pe + (long long)bs * Dd;
        float c0 = per[lane],      s0 = per[64 + lane];
        float c1 = per[32 + lane], s1 = per[96 + lane];
        float o0 = n0 * c0 - n2 * s0, o1 = n1 * c1 - n3 * s1;
        float o2 = n0 * s0 + n2 * c0, o3 = n1 * s1 + n3 * c1;
        const int b = bs >> 11, s = bs & 2047;
        long long base = ((long long)(b * KVh + kvh) * Ss + s) * Dd;
        wsb(kh, kl, base + lane, o0);       wsb(kh, kl, base + lane + 32, o1);
        wsb(kh, kl, base + lane + 64, o2);  wsb(kh, kl, base + lane + 96, o3);
    } else {  // V
        const int t = task - 98304;
        const int bs = t >> 3, kvh = t & 7;
        const float* src = qkv + (long long)bs * NQKV + (Hh + KVh) * Dd + kvh * Dd;
        const int b = bs >> 11, s = bs & 2047;
        long long base = ((long long)(b * KVh + kvh) * Ss + s) * Dd;
        wsb(vh, vl, base + lane,      src[lane]);
        wsb(vh, vl, base + lane + 32, src[lane + 32]);
        wsb(vh, vl, base + lane + 64, src[lane + 64]);
        wsb(vh, vl, base + lane + 96, src[lane + 96]);
    }
}

// ---------------- V transpose: [B,KV,S,D] -> [B,KV,D,S] (hi+lo) ----------------
__global__ void k_vt(const bf16* __restrict__ vh, const bf16* __restrict__ vl,
                     bf16* __restrict__ vth, bf16* __restrict__ vtl) {
    __shared__ bf16 th[32][33], tl[32][33];
    const int bz = blockIdx.z;
    const long long base = (long long)bz * Ss * Dd;
    const int s0 = blockIdx.x * 32, d0 = blockIdx.y * 32;
    const int tx = threadIdx.x, ty = threadIdx.y;
#pragma unroll
    for (int j = 0; j < 4; j++) {
        int r = ty + j * 8;
        th[r][tx] = vh[base + (long long)(s0 + r) * Dd + d0 + tx];
        tl[r][tx] = vl[base + (long long)(s0 + r) * Dd + d0 + tx];
    }
    __syncthreads();
#pragma unroll
    for (int j = 0; j < 4; j++) {
        int r = ty + j * 8;
        vth[base + (long long)(d0 + r) * Ss + s0 + tx] = th[tx][r];
        vtl[base + (long long)(d0 + r) * Ss + s0 + tx] = tl[tx][r];
    }
}

// ---------------- launch -----------------------------------------------------
extern "C" void kernel_launch(void* const* d_in, const int* in_sizes, int n_in,
                              void* d_out, int out_size) {
    (void)in_sizes; (void)n_in; (void)out_size;
    const float* x   = (const float*)d_in[0];
    const float* pe  = (const float*)d_in[1];
    const float* qw  = (const float*)d_in[2];
    const float* kw  = (const float*)d_in[3];
    const float* vw  = (const float*)d_in[4];
    const float* ow  = (const float*)d_in[5];
    const float* qnw = (const float*)d_in[6];
    const float* knw = (const float*)d_in[7];
    float* out = (float*)d_out;

    bf16 *xh, *xl, *wh, *wl, *owh, *owl;
    bf16 *qh, *ql, *kh, *kl, *vh, *vl, *vth, *vtl, *aoh, *aol;
    float *qkvp, *sc, *pm, *ps, *sm, *si;
    cudaGetSymbolAddress((void**)&xh, g_xh);   cudaGetSymbolAddress((void**)&xl, g_xl);
    cudaGetSymbolAddress((void**)&wh, g_wh);   cudaGetSymbolAddress((void**)&wl, g_wl);
    cudaGetSymbolAddress((void**)&owh, g_owh); cudaGetSymbolAddress((void**)&owl, g_owl);
    cudaGetSymbolAddress((void**)&qkvp, g_qkv);
    cudaGetSymbolAddress((void**)&qh, g_qh);   cudaGetSymbolAddress((void**)&ql, g_ql);
    cudaGetSymbolAddress((void**)&kh, g_kh);   cudaGetSymbolAddress((void**)&kl, g_kl);
    cudaGetSymbolAddress((void**)&vh, g_vh);   cudaGetSymbolAddress((void**)&vl, g_vl);
    cudaGetSymbolAddress((void**)&vth, g_vth); cudaGetSymbolAddress((void**)&vtl, g_vtl);
    cudaGetSymbolAddress((void**)&sc, g_sc);
    cudaGetSymbolAddress((void**)&pm, g_pm);   cudaGetSymbolAddress((void**)&ps, g_ps);
    cudaGetSymbolAddress((void**)&sm, g_sm);   cudaGetSymbolAddress((void**)&si, g_si);
    cudaGetSymbolAddress((void**)&aoh, g_aoh); cudaGetSymbolAddress((void**)&aol, g_aol);

    cudaFuncSetAttribute((const void*)k_mm<0, false>,
                         cudaFuncAttributeMaxDynamicSharedMemorySize, SMEM_MM);
    cudaFuncSetAttribute((const void*)k_mm<3, false>,
                         cudaFuncAttributeMaxDynamicSharedMemorySize, SMEM_MM);
    cudaFuncSetAttribute((const void*)k_mm<1, true>,
                         cudaFuncAttributeMaxDynamicSharedMemorySize, SMEM_MM);

    // 1) bf16 splits of x and all weights (single launch)
    k_split_all<<<(F4_TOT + 255) / 256, 256>>>(x, qw, kw, vw, ow);

    // 2) QKV projection -> g_qkv fp32
    {
        dim3 g(NQKV / 128, MROWS / 128, 1);
        k_mm<0, false><<<g, 256, SMEM_MM>>>(
            xh, xl, wh, wl, qkvp, nullptr, nullptr,
            HID, NQKV, 0, 0, 0, 0, 0, 0, 1, 1, 0,
            nullptr, nullptr, nullptr, nullptr, nullptr);
    }

    // 3) RMSNorm + RoPE + bf16 split -> q/k/v [B,(KV)H,S,D]
    k_qkvpost<<<32768, 128>>>(qkvp, pe, qnw, knw, qh, ql, kh, kl, vh, vl);

    // 4) V transpose -> [B,KV,D,S]
    {
        dim3 g(Ss / 32, Dd / 32, Bz * KVh);
        k_vt<<<g, dim3(32, 8)>>>(vh, vl, vth, vtl);
    }

    // 5) scores = q @ k^T (causal tile-skip) -> g_sc fp32 + per-tile stats
    {
        dim3 g(Ss / 128, Ss / 128, Bz * Hh);
        k_mm<3, false><<<g, 256, SMEM_MM>>>(
            qh, ql, kh, kl, sc, nullptr, nullptr, Dd, Ss,
            (long long)Hh * Ss * Dd, (long long)Ss * Dd,
            (long long)KVh * Ss * Dd, (long long)Ss * Dd,
            (long long)Hh * Ss * Ss, (long long)Ss * Ss,
            Hh, Hh / KVh, 1,
            nullptr, nullptr, nullptr, pm, ps);
    }

    // 6) reduce per-tile stats -> per-row (max, 1/sum)
    k_sred<<<(int)(NROW + 255) / 256, 256>>>(pm, ps, sm, si);

    // 7) attnout = softmax(scores) @ V^T (CONV: on-the-fly P, 3-term, K-trim)
    {
        dim3 g(1, Ss / 128, Bz * Hh);
        k_mm<1, true><<<g, 256, SMEM_MM>>>(
            nullptr, nullptr, vth, vtl, nullptr, aoh, aol, Ss, Hh * Dd,
            0, 0,
            (long long)KVh * Dd * Ss, (long long)Dd * Ss,
            (long long)Ss * Hh * Dd, (long long)Dd,
            Hh, Hh / KVh, 2,
            sc, sm, si, nullptr, nullptr);
    }

    // 8) out = attnout @ o_w^T -> d_out [4096,2048] fp32
    {
        dim3 g(HID / 128, MROWS / 128, 1);
        k_mm<0, false><<<g, 256, SMEM_MM>>>(
            aoh, aol, owh, owl, out, nullptr, nullptr,
            Hh * Dd, HID, 0, 0, 0, 0, 0, 0, 1, 1, 0,
            nullptr, nullptr, nullptr, nullptr, nullptr);
    }
}